// round 17
// baseline (speedup 1.0000x reference)
#include <cuda_runtime.h>
#include <stdint.h>

#define NN 100000
#define NE 1000000
#define D  64

typedef unsigned long long u64;

// Scratch: scatter-sum accumulator [NN, D].
__device__ __align__(256) float g_agg[(size_t)NN * D];

// Runtime dtype flag for edge_index: 1 = int64, 0 = int32.
__device__ int g_idx_is64;

// ---------------------------------------------------------------------------
// Packed fp32x2 helpers (sm_100+): 2 FMAs per issue slot on the fp32 pipe.
// ---------------------------------------------------------------------------
__device__ __forceinline__ u64 pack2(float lo, float hi) {
    u64 r; asm("mov.b64 %0, {%1, %2};" : "=l"(r) : "f"(lo), "f"(hi)); return r;
}
__device__ __forceinline__ void unpack2(u64 v, float& lo, float& hi) {
    asm("mov.b64 {%0, %1}, %2;" : "=f"(lo), "=f"(hi) : "l"(v));
}
__device__ __forceinline__ u64 fma2(u64 a, u64 b, u64 c) {
    u64 d; asm("fma.rn.f32x2 %0, %1, %2, %3;" : "=l"(d) : "l"(a), "l"(b), "l"(c));
    return d;
}

// ---------------------------------------------------------------------------
// Detect edge_index dtype (see round-13 rationale).
// ---------------------------------------------------------------------------
__global__ void detect_kernel(const long long* eidx64) {
    if (threadIdx.x == 0 && blockIdx.x == 0) {
        int all_ok = 1;
        for (int i = 0; i < 64; i++) {
            long long v = eidx64[i];
            if (v < 0 || v >= NN) { all_ok = 0; break; }
        }
        g_idx_is64 = all_ok;
    }
}

__global__ void zero_agg_kernel() {
    size_t i = (size_t)blockIdx.x * blockDim.x + threadIdx.x;
    const size_t total = (size_t)NN * D / 4;
    if (i < total) {
        float4 z; z.x = 0.f; z.y = 0.f; z.z = 0.f; z.w = 0.f;
        reinterpret_cast<float4*>(g_agg)[i] = z;
    }
}

__device__ __forceinline__ void red_add_v4(float* p, float a, float b, float c, float d) {
    asm volatile("red.global.add.v4.f32 [%0], {%1, %2, %3, %4};"
                 :: "l"(p), "f"(a), "f"(b), "f"(c), "f"(d) : "memory");
}

// ---------------------------------------------------------------------------
// Edge kernel
// ---------------------------------------------------------------------------
constexpr int TE = 128;
constexpr int XS = 65;    // 8*65 mod 32 = 8 -> conflict-free row reads

struct __align__(16) ESmem {
    float w1[D * D];
    float w2[D * D];
    float b1[D];
    float b2[D];
    float x[TE * XS];
    int   col[TE];
};

__global__ __launch_bounds__(128) void edge_kernel(
    const float* __restrict__ x,
    const void* __restrict__ eidx_raw,
    const float* __restrict__ w1, const float* __restrict__ b1,
    const float* __restrict__ w2, const float* __restrict__ b2)
{
    extern __shared__ char smem_raw[];
    ESmem& s = *reinterpret_cast<ESmem*>(smem_raw);
    const int tid = threadIdx.x;
    const int use64 = g_idx_is64;
    const int*       e32 = reinterpret_cast<const int*>(eidx_raw);
    const long long* e64 = reinterpret_cast<const long long*>(eidx_raw);

    for (int i = tid; i < D * D / 4; i += 128) {
        reinterpret_cast<float4*>(s.w1)[i] = reinterpret_cast<const float4*>(w1)[i];
        reinterpret_cast<float4*>(s.w2)[i] = reinterpret_cast<const float4*>(w2)[i];
    }
    if (tid < D) { s.b1[tid] = b1[tid]; s.b2[tid] = b2[tid]; }

    const int eg = tid >> 3;
    const int cg = tid & 7;
    const int e0 = eg * 8;
    const int c0 = cg * 8;
    const int ntiles = (NE + TE - 1) / TE;

    for (int tile = blockIdx.x; tile < ntiles; tile += gridDim.x) {
        __syncthreads();

        // ---- gather ----
        const int e = tile * TE + tid;
        int r = 0, c = -1;
        if (e < NE) {
            if (use64) { r = (int)e64[e]; c = (int)e64[NE + e]; }
            else       { r = e32[e];      c = e32[NE + e]; }
            r = min(max(r, 0), NN - 1);
            c = min(c, NN - 1);
        }
        s.col[tid] = c;
        const float4* xr = reinterpret_cast<const float4*>(x + (size_t)r * D);
        #pragma unroll
        for (int j = 0; j < 16; j++) {
            float4 v = xr[j];
            float* dst = &s.x[tid * XS + 4 * j];
            dst[0] = v.x; dst[1] = v.y; dst[2] = v.z; dst[3] = v.w;
        }
        __syncthreads();

        // ---- layer 1: H = relu(X @ W1 + b1), packed fp32x2 ----
        u64 acc[8][4];
        {
            const u64* bp = reinterpret_cast<const u64*>(&s.b1[c0]);
            u64 bb0 = bp[0], bb1 = bp[1], bb2 = bp[2], bb3 = bp[3];
            #pragma unroll
            for (int i = 0; i < 8; i++) {
                acc[i][0] = bb0; acc[i][1] = bb1; acc[i][2] = bb2; acc[i][3] = bb3;
            }
        }
        #pragma unroll 4
        for (int k = 0; k < D; k++) {
            u64 ap[8];
            #pragma unroll
            for (int i = 0; i < 8; i++) {
                float av = s.x[(e0 + i) * XS + k];
                ap[i] = pack2(av, av);
            }
            ulonglong2 w01 = *reinterpret_cast<const ulonglong2*>(&s.w1[k * D + c0]);
            ulonglong2 w23 = *reinterpret_cast<const ulonglong2*>(&s.w1[k * D + c0 + 4]);
            #pragma unroll
            for (int i = 0; i < 8; i++) {
                acc[i][0] = fma2(ap[i], w01.x, acc[i][0]);
                acc[i][1] = fma2(ap[i], w01.y, acc[i][1]);
                acc[i][2] = fma2(ap[i], w23.x, acc[i][2]);
                acc[i][3] = fma2(ap[i], w23.y, acc[i][3]);
            }
        }
        __syncthreads();

        // relu + store H in place of X
        #pragma unroll
        for (int i = 0; i < 8; i++) {
            #pragma unroll
            for (int j = 0; j < 4; j++) {
                float lo, hi; unpack2(acc[i][j], lo, hi);
                s.x[(e0 + i) * XS + c0 + 2 * j]     = fmaxf(lo, 0.f);
                s.x[(e0 + i) * XS + c0 + 2 * j + 1] = fmaxf(hi, 0.f);
            }
        }
        __syncthreads();

        // ---- layer 2: M = H @ W2 + b2 ----
        {
            const u64* bp = reinterpret_cast<const u64*>(&s.b2[c0]);
            u64 bb0 = bp[0], bb1 = bp[1], bb2 = bp[2], bb3 = bp[3];
            #pragma unroll
            for (int i = 0; i < 8; i++) {
                acc[i][0] = bb0; acc[i][1] = bb1; acc[i][2] = bb2; acc[i][3] = bb3;
            }
        }
        #pragma unroll 4
        for (int k = 0; k < D; k++) {
            u64 ap[8];
            #pragma unroll
            for (int i = 0; i < 8; i++) {
                float av = s.x[(e0 + i) * XS + k];
                ap[i] = pack2(av, av);
            }
            ulonglong2 w01 = *reinterpret_cast<const ulonglong2*>(&s.w2[k * D + c0]);
            ulonglong2 w23 = *reinterpret_cast<const ulonglong2*>(&s.w2[k * D + c0 + 4]);
            #pragma unroll
            for (int i = 0; i < 8; i++) {
                acc[i][0] = fma2(ap[i], w01.x, acc[i][0]);
                acc[i][1] = fma2(ap[i], w01.y, acc[i][1]);
                acc[i][2] = fma2(ap[i], w23.x, acc[i][2]);
                acc[i][3] = fma2(ap[i], w23.y, acc[i][3]);
            }
        }

        // ---- scatter-add into g_agg[col] ----
        #pragma unroll
        for (int i = 0; i < 8; i++) {
            int cc = s.col[e0 + i];
            if (cc >= 0) {
                float v0, v1, v2, v3, v4, v5, v6, v7;
                unpack2(acc[i][0], v0, v1);
                unpack2(acc[i][1], v2, v3);
                unpack2(acc[i][2], v4, v5);
                unpack2(acc[i][3], v6, v7);
                float* dst = g_agg + (size_t)cc * D + c0;
                red_add_v4(dst,     v0, v1, v2, v3);
                red_add_v4(dst + 4, v4, v5, v6, v7);
            }
        }
    }
}

// ---------------------------------------------------------------------------
// Node kernel
// ---------------------------------------------------------------------------
constexpr int TN  = 128;
constexpr int NXS = 129;   // 8*129 mod 32 = 8 -> conflict-free row reads

struct __align__(16) NSmem {
    float w1[2 * D * D];
    float w2[D * D];
    float b1[D];
    float b2[D];
    float xa[TN * NXS];
};

__global__ __launch_bounds__(128) void node_kernel(
    const float* __restrict__ x,
    const float* __restrict__ w1, const float* __restrict__ b1,
    const float* __restrict__ w2, const float* __restrict__ b2,
    float* __restrict__ out)
{
    extern __shared__ char smem_raw[];
    NSmem& s = *reinterpret_cast<NSmem*>(smem_raw);
    const int tid = threadIdx.x;

    for (int i = tid; i < 2 * D * D / 4; i += 128)
        reinterpret_cast<float4*>(s.w1)[i] = reinterpret_cast<const float4*>(w1)[i];
    for (int i = tid; i < D * D / 4; i += 128)
        reinterpret_cast<float4*>(s.w2)[i] = reinterpret_cast<const float4*>(w2)[i];
    if (tid < D) { s.b1[tid] = b1[tid]; s.b2[tid] = b2[tid]; }

    const int ng = tid >> 3;
    const int cg = tid & 7;
    const int n0 = ng * 8;
    const int c0 = cg * 8;
    const int ntiles = (NN + TN - 1) / TN;

    for (int tile = blockIdx.x; tile < ntiles; tile += gridDim.x) {
        __syncthreads();

        // ---- gather [x | agg] ----
        const int n = tile * TN + tid;
        const int src = (n < NN) ? n : 0;
        const float4* xr = reinterpret_cast<const float4*>(x + (size_t)src * D);
        const float4* ar = reinterpret_cast<const float4*>(g_agg + (size_t)src * D);
        #pragma unroll
        for (int j = 0; j < 16; j++) {
            float4 v = xr[j];
            float* dst = &s.xa[tid * NXS + 4 * j];
            dst[0] = v.x; dst[1] = v.y; dst[2] = v.z; dst[3] = v.w;
        }
        #pragma unroll
        for (int j = 0; j < 16; j++) {
            float4 v = ar[j];
            float* dst = &s.xa[tid * NXS + D + 4 * j];
            dst[0] = v.x; dst[1] = v.y; dst[2] = v.z; dst[3] = v.w;
        }
        __syncthreads();

        // ---- layer 1: K = 128, packed fp32x2 ----
        u64 acc[8][4];
        {
            const u64* bp = reinterpret_cast<const u64*>(&s.b1[c0]);
            u64 bb0 = bp[0], bb1 = bp[1], bb2 = bp[2], bb3 = bp[3];
            #pragma unroll
            for (int i = 0; i < 8; i++) {
                acc[i][0] = bb0; acc[i][1] = bb1; acc[i][2] = bb2; acc[i][3] = bb3;
            }
        }
        #pragma unroll 4
        for (int k = 0; k < 2 * D; k++) {
            u64 ap[8];
            #pragma unroll
            for (int i = 0; i < 8; i++) {
                float av = s.xa[(n0 + i) * NXS + k];
                ap[i] = pack2(av, av);
            }
            ulonglong2 w01 = *reinterpret_cast<const ulonglong2*>(&s.w1[k * D + c0]);
            ulonglong2 w23 = *reinterpret_cast<const ulonglong2*>(&s.w1[k * D + c0 + 4]);
            #pragma unroll
            for (int i = 0; i < 8; i++) {
                acc[i][0] = fma2(ap[i], w01.x, acc[i][0]);
                acc[i][1] = fma2(ap[i], w01.y, acc[i][1]);
                acc[i][2] = fma2(ap[i], w23.x, acc[i][2]);
                acc[i][3] = fma2(ap[i], w23.y, acc[i][3]);
            }
        }
        __syncthreads();

        #pragma unroll
        for (int i = 0; i < 8; i++) {
            #pragma unroll
            for (int j = 0; j < 4; j++) {
                float lo, hi; unpack2(acc[i][j], lo, hi);
                s.xa[(n0 + i) * NXS + c0 + 2 * j]     = fmaxf(lo, 0.f);
                s.xa[(n0 + i) * NXS + c0 + 2 * j + 1] = fmaxf(hi, 0.f);
            }
        }
        __syncthreads();

        // ---- layer 2: K = 64 ----
        {
            const u64* bp = reinterpret_cast<const u64*>(&s.b2[c0]);
            u64 bb0 = bp[0], bb1 = bp[1], bb2 = bp[2], bb3 = bp[3];
            #pragma unroll
            for (int i = 0; i < 8; i++) {
                acc[i][0] = bb0; acc[i][1] = bb1; acc[i][2] = bb2; acc[i][3] = bb3;
            }
        }
        #pragma unroll 4
        for (int k = 0; k < D; k++) {
            u64 ap[8];
            #pragma unroll
            for (int i = 0; i < 8; i++) {
                float av = s.xa[(n0 + i) * NXS + k];
                ap[i] = pack2(av, av);
            }
            ulonglong2 w01 = *reinterpret_cast<const ulonglong2*>(&s.w2[k * D + c0]);
            ulonglong2 w23 = *reinterpret_cast<const ulonglong2*>(&s.w2[k * D + c0 + 4]);
            #pragma unroll
            for (int i = 0; i < 8; i++) {
                acc[i][0] = fma2(ap[i], w01.x, acc[i][0]);
                acc[i][1] = fma2(ap[i], w01.y, acc[i][1]);
                acc[i][2] = fma2(ap[i], w23.x, acc[i][2]);
                acc[i][3] = fma2(ap[i], w23.y, acc[i][3]);
            }
        }

        // ---- write output ----
        #pragma unroll
        for (int i = 0; i < 8; i++) {
            int nn = tile * TN + n0 + i;
            if (nn < NN) {
                float4 v0, v1;
                unpack2(acc[i][0], v0.x, v0.y);
                unpack2(acc[i][1], v0.z, v0.w);
                unpack2(acc[i][2], v1.x, v1.y);
                unpack2(acc[i][3], v1.z, v1.w);
                float4* op = reinterpret_cast<float4*>(out + (size_t)nn * D + c0);
                op[0] = v0; op[1] = v1;
            }
        }
    }
}

// ---------------------------------------------------------------------------
// Launch
// ---------------------------------------------------------------------------
extern "C" void kernel_launch(void* const* d_in, const int* in_sizes, int n_in,
                              void* d_out, int out_size) {
    const float* x    = (const float*)d_in[0];
    const void*  eidx = d_in[1];
    const float* mw1 = (const float*)d_in[3];
    const float* mb1 = (const float*)d_in[4];
    const float* mw2 = (const float*)d_in[5];
    const float* mb2 = (const float*)d_in[6];
    const float* ow1 = (const float*)d_in[7];
    const float* ob1 = (const float*)d_in[8];
    const float* ow2 = (const float*)d_in[9];
    const float* ob2 = (const float*)d_in[10];
    float* out = (float*)d_out;

    cudaFuncSetAttribute(edge_kernel, cudaFuncAttributeMaxDynamicSharedMemorySize,
                         (int)sizeof(ESmem));
    cudaFuncSetAttribute(node_kernel, cudaFuncAttributeMaxDynamicSharedMemorySize,
                         (int)sizeof(NSmem));

    detect_kernel<<<1, 32>>>((const long long*)eidx);

    const int zero_elems = NN * D / 4;
    zero_agg_kernel<<<(zero_elems + 255) / 256, 256>>>();

    // 3 blocks/SM (~66.8 KB smem each)
    edge_kernel<<<444, 128, sizeof(ESmem)>>>(x, eidx, mw1, mb1, mw2, mb2);

    // try 2 blocks/SM (2 x 113 KB); grid-stride keeps correctness either way
    node_kernel<<<296, 128, sizeof(NSmem)>>>(x, ow1, ob1, ow2, ob2, out);
}